// round 4
// baseline (speedup 1.0000x reference)
#include <cuda_runtime.h>
#include <math.h>
#include <stdint.h>

#define Bb   8
#define Ss   1024
#define Dd   768
#define Hh   12
#define HDd  64
#define HIDh 3072
#define Mm   (Bb*Ss)   // 8192

// ---------------- scratch (device globals; no allocs allowed) ----------------
// tf32-bit payloads (uint32)
__device__ uint32_t g_q  [(size_t)Mm*Dd];
__device__ uint32_t g_k  [(size_t)Mm*Dd];
__device__ uint32_t g_v  [(size_t)Mm*Dd];
__device__ uint32_t g_ln2[(size_t)Mm*Dd];
__device__ uint32_t g_h1 [(size_t)Mm*HIDh];
__device__ uint32_t g_xc [(size_t)Mm*Dd];
__device__ uint32_t g_wq [(size_t)Dd*Dd];
__device__ uint32_t g_wk [(size_t)Dd*Dd];
__device__ uint32_t g_wv [(size_t)Dd*Dd];
__device__ uint32_t g_win[(size_t)Dd*HIDh];
__device__ uint32_t g_wout[(size_t)HIDh*Dd];
// fp32
__device__ float g_ctx[(size_t)Mm*Dd];
__device__ float g_y  [(size_t)Mm*Dd];

__device__ __forceinline__ float gelu_exact(float x) {
    return 0.5f * x * (1.0f + erff(x * 0.70710678118654752f));
}

__device__ __forceinline__ uint32_t f2tf32(float f) {
    uint32_t r;
    asm("cvt.rna.tf32.f32 %0, %1;" : "=r"(r) : "f"(f));
    return r;
}

__device__ __forceinline__ void cp_async16(uint32_t saddr, const void* gaddr) {
    asm volatile("cp.async.cg.shared.global [%0], [%1], 16;\n" :: "r"(saddr), "l"(gaddr));
}

__device__ __forceinline__ void mma_tf32(float* c, const uint32_t* a,
                                         uint32_t b0, uint32_t b1) {
    asm volatile(
        "mma.sync.aligned.m16n8k8.row.col.f32.tf32.tf32.f32 "
        "{%0,%1,%2,%3},{%4,%5,%6,%7},{%8,%9},{%0,%1,%2,%3};"
        : "+f"(c[0]), "+f"(c[1]), "+f"(c[2]), "+f"(c[3])
        : "r"(a[0]), "r"(a[1]), "r"(a[2]), "r"(a[3]), "r"(b0), "r"(b1));
}

// ---------------- prep: fp32 -> tf32 bits ------------------------------------
__global__ __launch_bounds__(256) void cvt_tf32(const float* __restrict__ src,
                                                int which, int n4)
{
    uint32_t* dst = which == 0 ? g_xc
                  : which == 1 ? g_wq
                  : which == 2 ? g_wk
                  : which == 3 ? g_wv
                  : which == 4 ? g_win : g_wout;
    int i = blockIdx.x * 256 + threadIdx.x;
    if (i < n4) {
        float4 f = ((const float4*)src)[i];
        uint4 u;
        u.x = f2tf32(f.x); u.y = f2tf32(f.y);
        u.z = f2tf32(f.z); u.w = f2tf32(f.w);
        ((uint4*)dst)[i] = u;
    }
}

// =====================================================================
// TF32 tensor-core GEMM, operands pre-converted to tf32 bits.
// BM=128, BN=128, BK=16, 256 threads (8 warps 2x4), warp tile 64x32.
// MODE 0: A=g_xc, B=g_wq/wk/wv -> g_q/g_k/g_v (tf32 bits; Q scaled 1/8)
// MODE 1: A=g_ln2, B=g_win     -> g_h1 = tf32(gelu(acc+bias))
// MODE 2: A=g_h1,  B=g_wout    -> Cout = gelu(acc+bias) + g_y   (fp32)
// =====================================================================
#define ASTRIDE 20
#define BSTRIDE 136

template<int MODE>
__global__ __launch_bounds__(256) void gemm_tf32(
    const float* __restrict__ bias, float* __restrict__ Cout,
    int N, int K, int which)
{
    __shared__ uint32_t As[2][128 * ASTRIDE];
    __shared__ uint32_t Bs[2][16 * BSTRIDE];

    const uint32_t* A = (MODE == 0) ? g_xc : (MODE == 1 ? g_ln2 : g_h1);
    const uint32_t* Bw = (MODE == 0)
        ? (which == 0 ? g_wq : (which == 1 ? g_wk : g_wv))
        : (MODE == 1 ? g_win : g_wout);

    const int tid  = threadIdx.x;
    const int lane = tid & 31;
    const int warp = tid >> 5;
    const int warpM = warp & 1;
    const int warpN = warp >> 1;
    const int quad = lane >> 2;
    const int tkid = lane & 3;

    const int m0 = blockIdx.y * 128;
    const int n0 = blockIdx.x * 128;

    const int a_row0 = (tid) >> 2,        a_c0 = (tid & 3) * 4;
    const int a_row1 = (tid + 256) >> 2,  a_c1 = a_c0;
    const int b_r0 = tid >> 5,            b_c0 = (tid & 31) * 4;
    const int b_r1 = (tid >> 5) + 8,      b_c1 = b_c0;

    uint32_t sA = (uint32_t)__cvta_generic_to_shared(&As[0][0]);
    uint32_t sB = (uint32_t)__cvta_generic_to_shared(&Bs[0][0]);
    const uint32_t sAsz = 128 * ASTRIDE * 4;
    const uint32_t sBsz = 16 * BSTRIDE * 4;

    const int KT = K / 16;

    auto issue_tile = [&](int kt, int buf) {
        int k0 = kt * 16;
        cp_async16(sA + buf * sAsz + (a_row0 * ASTRIDE + a_c0) * 4,
                   A + (size_t)(m0 + a_row0) * K + k0 + a_c0);
        cp_async16(sA + buf * sAsz + (a_row1 * ASTRIDE + a_c1) * 4,
                   A + (size_t)(m0 + a_row1) * K + k0 + a_c1);
        cp_async16(sB + buf * sBsz + (b_r0 * BSTRIDE + b_c0) * 4,
                   Bw + (size_t)(k0 + b_r0) * N + n0 + b_c0);
        cp_async16(sB + buf * sBsz + (b_r1 * BSTRIDE + b_c1) * 4,
                   Bw + (size_t)(k0 + b_r1) * N + n0 + b_c1);
        asm volatile("cp.async.commit_group;\n");
    };

    float acc[4][4][4];
    #pragma unroll
    for (int i = 0; i < 4; i++)
        #pragma unroll
        for (int j = 0; j < 4; j++)
            #pragma unroll
            for (int r = 0; r < 4; r++) acc[i][j][r] = 0.0f;

    issue_tile(0, 0);

    for (int kt = 0; kt < KT; kt++) {
        const int buf = kt & 1;
        if (kt + 1 < KT) {
            issue_tile(kt + 1, buf ^ 1);
            asm volatile("cp.async.wait_group 1;\n");
        } else {
            asm volatile("cp.async.wait_group 0;\n");
        }
        __syncthreads();

        const uint32_t* Ab = &As[buf][0];
        const uint32_t* Bbp = &Bs[buf][0];

        #pragma unroll
        for (int ks = 0; ks < 2; ks++) {
            const int kb = ks * 8;
            uint32_t afr[4][4];
            #pragma unroll
            for (int tm = 0; tm < 4; tm++) {
                int mr = warpM * 64 + tm * 16 + quad;
                afr[tm][0] = Ab[(mr    ) * ASTRIDE + kb + tkid    ];
                afr[tm][1] = Ab[(mr + 8) * ASTRIDE + kb + tkid    ];
                afr[tm][2] = Ab[(mr    ) * ASTRIDE + kb + tkid + 4];
                afr[tm][3] = Ab[(mr + 8) * ASTRIDE + kb + tkid + 4];
            }
            uint32_t bfr[4][2];
            #pragma unroll
            for (int tn = 0; tn < 4; tn++) {
                int nc = warpN * 32 + tn * 8 + quad;
                bfr[tn][0] = Bbp[(kb + tkid    ) * BSTRIDE + nc];
                bfr[tn][1] = Bbp[(kb + tkid + 4) * BSTRIDE + nc];
            }
            #pragma unroll
            for (int tm = 0; tm < 4; tm++)
                #pragma unroll
                for (int tn = 0; tn < 4; tn++)
                    mma_tf32(acc[tm][tn], afr[tm], bfr[tn][0], bfr[tn][1]);
        }
        __syncthreads();
    }

    uint32_t* qkv_out = (MODE == 0)
        ? (which == 0 ? g_q : (which == 1 ? g_k : g_v)) : nullptr;
    const float qscale = (MODE == 0 && which == 0) ? 0.125f : 1.0f;

    #pragma unroll
    for (int tm = 0; tm < 4; tm++) {
        #pragma unroll
        for (int tn = 0; tn < 4; tn++) {
            #pragma unroll
            for (int r = 0; r < 4; r++) {
                int m = m0 + warpM * 64 + tm * 16 + quad + (r >= 2 ? 8 : 0);
                int n = n0 + warpN * 32 + tn * 8 + tkid * 2 + (r & 1);
                float val = acc[tm][tn][r] + bias[n];
                if (MODE == 0) {
                    int b = m >> 10, s = m & 1023;
                    int h = n >> 6, hd = n & 63;
                    qkv_out[(((size_t)b * Hh + h) * Ss + s) * HDd + hd] =
                        f2tf32(val * qscale);
                } else if (MODE == 1) {
                    g_h1[(size_t)m * N + n] = f2tf32(gelu_exact(val));
                } else {
                    Cout[(size_t)m * N + n] =
                        gelu_exact(val) + g_y[(size_t)m * N + n];
                }
            }
        }
    }
}

// =====================================================================
// Tensor-core flash attention; Q/K/V pre-converted tf32 bits, no cvt
// in the mainloop (P converted once at store).
// =====================================================================
#define KSTR 68
#define PSTR 36

__global__ __launch_bounds__(128) void attn_tc(void)
{
    __shared__ uint32_t Ks[2][32 * KSTR];
    __shared__ uint32_t Vs[2][32 * KSTR];
    __shared__ uint32_t Pb[4][16 * PSTR];

    const int bh   = blockIdx.y;
    const int tid  = threadIdx.x;
    const int warp = tid >> 5;
    const int lane = tid & 31;
    const int quad = lane >> 2;
    const int tkid = lane & 3;

    const int q0 = blockIdx.x * 64 + warp * 16;
    const uint32_t* qbase = g_q + ((size_t)bh * Ss + q0) * HDd;
    const uint32_t* kbase = g_k + (size_t)bh * Ss * HDd;
    const uint32_t* vbase = g_v + (size_t)bh * Ss * HDd;

    uint32_t qf[8][4];
    #pragma unroll
    for (int kk = 0; kk < 8; kk++) {
        int c = kk * 8 + tkid;
        qf[kk][0] = qbase[(quad    ) * HDd + c    ];
        qf[kk][1] = qbase[(quad + 8) * HDd + c    ];
        qf[kk][2] = qbase[(quad    ) * HDd + c + 4];
        qf[kk][3] = qbase[(quad + 8) * HDd + c + 4];
    }

    float o[8][4];
    #pragma unroll
    for (int j = 0; j < 8; j++)
        #pragma unroll
        for (int r = 0; r < 4; r++) o[j][r] = 0.0f;
    float mrow[2] = {-1e30f, -1e30f};
    float lrow[2] = {0.0f, 0.0f};

    uint32_t sK = (uint32_t)__cvta_generic_to_shared(&Ks[0][0]);
    uint32_t sV = (uint32_t)__cvta_generic_to_shared(&Vs[0][0]);
    const uint32_t bufsz = 32 * KSTR * 4;

    auto load_tile = [&](int t, int buf) {
        const uint32_t* kp = kbase + (size_t)t * 32 * HDd;
        const uint32_t* vp = vbase + (size_t)t * 32 * HDd;
        #pragma unroll
        for (int i = 0; i < 4; i++) {
            int idx = tid + i * 128;
            int r = idx >> 4, c4 = (idx & 15) * 4;
            cp_async16(sK + buf * bufsz + (r * KSTR + c4) * 4, kp + r * HDd + c4);
            cp_async16(sV + buf * bufsz + (r * KSTR + c4) * 4, vp + r * HDd + c4);
        }
        asm volatile("cp.async.commit_group;\n");
    };

    load_tile(0, 0);
    const int NT = Ss / 32;

    for (int t = 0; t < NT; t++) {
        const int buf = t & 1;
        if (t + 1 < NT) {
            load_tile(t + 1, buf ^ 1);
            asm volatile("cp.async.wait_group 1;\n");
        } else {
            asm volatile("cp.async.wait_group 0;\n");
        }
        __syncthreads();

        float sc[4][4];
        #pragma unroll
        for (int j = 0; j < 4; j++)
            #pragma unroll
            for (int r = 0; r < 4; r++) sc[j][r] = 0.0f;

        #pragma unroll
        for (int kk = 0; kk < 8; kk++) {
            #pragma unroll
            for (int j = 0; j < 4; j++) {
                const uint32_t* kr = &Ks[buf][(j * 8 + quad) * KSTR + kk * 8 + tkid];
                mma_tf32(sc[j], qf[kk], kr[0], kr[4]);
            }
        }

        #pragma unroll
        for (int r = 0; r < 2; r++) {
            float tmax = -1e30f;
            #pragma unroll
            for (int j = 0; j < 4; j++)
                tmax = fmaxf(tmax, fmaxf(sc[j][2 * r], sc[j][2 * r + 1]));
            tmax = fmaxf(tmax, __shfl_xor_sync(0xffffffffu, tmax, 1));
            tmax = fmaxf(tmax, __shfl_xor_sync(0xffffffffu, tmax, 2));

            float mnew = fmaxf(mrow[r], tmax);
            float corr = __expf(mrow[r] - mnew);
            mrow[r] = mnew;
            lrow[r] *= corr;
            #pragma unroll
            for (int j = 0; j < 8; j++) {
                o[j][2 * r]     *= corr;
                o[j][2 * r + 1] *= corr;
            }
        }

        __syncwarp();
        uint32_t* pw = &Pb[warp][0];
        #pragma unroll
        for (int j = 0; j < 4; j++) {
            float p0 = __expf(sc[j][0] - mrow[0]);
            float p1 = __expf(sc[j][1] - mrow[0]);
            float p2 = __expf(sc[j][2] - mrow[1]);
            float p3 = __expf(sc[j][3] - mrow[1]);
            lrow[0] += p0 + p1;
            lrow[1] += p2 + p3;
            int col = j * 8 + tkid * 2;
            uint2 u01 = make_uint2(f2tf32(p0), f2tf32(p1));
            uint2 u23 = make_uint2(f2tf32(p2), f2tf32(p3));
            *(uint2*)&pw[(quad    ) * PSTR + col] = u01;
            *(uint2*)&pw[(quad + 8) * PSTR + col] = u23;
        }
        __syncwarp();

        #pragma unroll
        for (int kk = 0; kk < 4; kk++) {
            uint32_t af[4];
            int c = kk * 8 + tkid;
            af[0] = pw[(quad    ) * PSTR + c    ];
            af[1] = pw[(quad + 8) * PSTR + c    ];
            af[2] = pw[(quad    ) * PSTR + c + 4];
            af[3] = pw[(quad + 8) * PSTR + c + 4];
            #pragma unroll
            for (int j = 0; j < 8; j++) {
                const uint32_t* vr = &Vs[buf][(kk * 8 + tkid) * KSTR + j * 8 + quad];
                mma_tf32(o[j], af, vr[0], vr[4 * KSTR]);
            }
        }
        __syncthreads();
    }

    #pragma unroll
    for (int r = 0; r < 2; r++) {
        lrow[r] += __shfl_xor_sync(0xffffffffu, lrow[r], 1);
        lrow[r] += __shfl_xor_sync(0xffffffffu, lrow[r], 2);
    }
    float inv0 = 1.0f / lrow[0];
    float inv1 = 1.0f / lrow[1];

    float* ob0 = g_ctx + ((size_t)bh * Ss + q0 + quad    ) * HDd;
    float* ob1 = g_ctx + ((size_t)bh * Ss + q0 + quad + 8) * HDd;
    #pragma unroll
    for (int j = 0; j < 8; j++) {
        int col = j * 8 + tkid * 2;
        *(float2*)&ob0[col] = make_float2(o[j][0] * inv0, o[j][1] * inv0);
        *(float2*)&ob1[col] = make_float2(o[j][2] * inv1, o[j][3] * inv1);
    }
}

// ---------------- LN1: y = x + LN(ctx[B,H,S,HD]) * g + b --------------------
__global__ __launch_bounds__(256) void ln1_add(
    const float* __restrict__ x, const float* __restrict__ g,
    const float* __restrict__ bta)
{
    const int row = blockIdx.x;
    const int b = row >> 10, s = row & 1023;
    const int tid = threadIdx.x;

    float vals[3];
    float sum = 0.0f, sq = 0.0f;
    #pragma unroll
    for (int i = 0; i < 3; i++) {
        int col = tid + i * 256;
        int h = col >> 6, hd = col & 63;
        float c = g_ctx[(((size_t)b * Hh + h) * Ss + s) * HDd + hd];
        vals[i] = c;
        sum += c;
        sq += c * c;
    }
    __shared__ float rs[256], rq[256];
    rs[tid] = sum; rq[tid] = sq;
    __syncthreads();
    for (int o = 128; o > 0; o >>= 1) {
        if (tid < o) { rs[tid] += rs[tid + o]; rq[tid] += rq[tid + o]; }
        __syncthreads();
    }
    float mu = rs[0] * (1.0f / Dd);
    float var = rq[0] * (1.0f / Dd) - mu * mu;
    float rstd = rsqrtf(var + 1e-5f);
    #pragma unroll
    for (int i = 0; i < 3; i++) {
        int col = tid + i * 256;
        float yv = x[(size_t)row * Dd + col] +
                   (vals[i] - mu) * rstd * g[col] + bta[col];
        g_y[(size_t)row * Dd + col] = yv;
    }
}

// ---------------- LN2: g_ln2 = tf32(LN(g_y) * g + b) ------------------------
__global__ __launch_bounds__(256) void ln2_kernel(
    const float* __restrict__ g, const float* __restrict__ bta)
{
    const int row = blockIdx.x;
    const int tid = threadIdx.x;

    float vals[3];
    float sum = 0.0f, sq = 0.0f;
    #pragma unroll
    for (int i = 0; i < 3; i++) {
        int col = tid + i * 256;
        float c = g_y[(size_t)row * Dd + col];
        vals[i] = c;
        sum += c;
        sq += c * c;
    }
    __shared__ float rs[256], rq[256];
    rs[tid] = sum; rq[tid] = sq;
    __syncthreads();
    for (int o = 128; o > 0; o >>= 1) {
        if (tid < o) { rs[tid] += rs[tid + o]; rq[tid] += rq[tid + o]; }
        __syncthreads();
    }
    float mu = rs[0] * (1.0f / Dd);
    float var = rq[0] * (1.0f / Dd) - mu * mu;
    float rstd = rsqrtf(var + 1e-5f);
    #pragma unroll
    for (int i = 0; i < 3; i++) {
        int col = tid + i * 256;
        g_ln2[(size_t)row * Dd + col] =
            f2tf32((vals[i] - mu) * rstd * g[col] + bta[col]);
    }
}

// ---------------- launch ----------------------------------------------------
extern "C" void kernel_launch(void* const* d_in, const int* in_sizes, int n_in,
                              void* d_out, int out_size)
{
    (void)in_sizes; (void)n_in; (void)out_size;
    const float* x     = (const float*)d_in[0];
    const float* wq    = (const float*)d_in[1];
    const float* bq    = (const float*)d_in[2];
    const float* wk    = (const float*)d_in[3];
    const float* bk    = (const float*)d_in[4];
    const float* wv    = (const float*)d_in[5];
    const float* bv    = (const float*)d_in[6];
    const float* ln1_g = (const float*)d_in[7];
    const float* ln1_b = (const float*)d_in[8];
    const float* ln2_g = (const float*)d_in[9];
    const float* ln2_b = (const float*)d_in[10];
    const float* w_in  = (const float*)d_in[11];
    const float* b_in  = (const float*)d_in[12];
    const float* w_out = (const float*)d_in[13];
    const float* b_out = (const float*)d_in[14];
    float* out = (float*)d_out;

    // prep: convert operands to tf32 bits
    cvt_tf32<<<(Mm*Dd/4 + 255)/256, 256>>>(x, 0, Mm*Dd/4);
    cvt_tf32<<<(Dd*Dd/4 + 255)/256, 256>>>(wq, 1, Dd*Dd/4);
    cvt_tf32<<<(Dd*Dd/4 + 255)/256, 256>>>(wk, 2, Dd*Dd/4);
    cvt_tf32<<<(Dd*Dd/4 + 255)/256, 256>>>(wv, 3, Dd*Dd/4);
    cvt_tf32<<<(Dd*HIDh/4 + 255)/256, 256>>>(w_in, 4, Dd*HIDh/4);
    cvt_tf32<<<(HIDh*Dd/4 + 255)/256, 256>>>(w_out, 5, HIDh*Dd/4);

    dim3 gq(Dd / 128, Mm / 128);
    gemm_tf32<0><<<gq, 256>>>(bq, nullptr, Dd, Dd, 0);
    gemm_tf32<0><<<gq, 256>>>(bk, nullptr, Dd, Dd, 1);
    gemm_tf32<0><<<gq, 256>>>(bv, nullptr, Dd, Dd, 2);

    dim3 ga(Ss / 64, Bb * Hh);
    attn_tc<<<ga, 128>>>();

    ln1_add<<<Mm, 256>>>(x, ln1_g, ln1_b);
    ln2_kernel<<<Mm, 256>>>(ln2_g, ln2_b);

    dim3 g1(HIDh / 128, Mm / 128);
    gemm_tf32<1><<<g1, 256>>>(b_in, nullptr, HIDh, Dd, 0);

    dim3 g2(Dd / 128, Mm / 128);
    gemm_tf32<2><<<g2, 256>>>(b_out, out, Dd, HIDh, 0);
}

// round 6
// speedup vs baseline: 1.7988x; 1.7988x over previous
#include <cuda_runtime.h>
#include <cuda_fp16.h>
#include <math.h>
#include <stdint.h>

#define Bb   8
#define Ss   1024
#define Dd   768
#define Hh   12
#define HDd  64
#define HIDh 3072
#define Mm   (Bb*Ss)   // 8192

// ---------------- scratch (device globals; no allocs allowed) ----------------
__device__ __half g_q   [(size_t)Mm*Dd];
__device__ __half g_k   [(size_t)Mm*Dd];
__device__ __half g_v   [(size_t)Mm*Dd];
__device__ __half g_ln2 [(size_t)Mm*Dd];
__device__ __half g_h1  [(size_t)Mm*HIDh];
__device__ __half g_xc  [(size_t)Mm*Dd];
__device__ __half g_wqT [(size_t)Dd*Dd];      // [N,K]
__device__ __half g_wkT [(size_t)Dd*Dd];
__device__ __half g_wvT [(size_t)Dd*Dd];
__device__ __half g_winT[(size_t)HIDh*Dd];    // [3072,768]
__device__ __half g_woutT[(size_t)Dd*HIDh];   // [768,3072]
__device__ float g_ctx[(size_t)Mm*Dd];
__device__ float g_y  [(size_t)Mm*Dd];

__device__ __forceinline__ float gelu_exact(float x) {
    return 0.5f * x * (1.0f + erff(x * 0.70710678118654752f));
}
__device__ __forceinline__ void cp_async16(uint32_t saddr, const void* gaddr) {
    asm volatile("cp.async.cg.shared.global [%0], [%1], 16;\n" :: "r"(saddr), "l"(gaddr));
}
__device__ __forceinline__ uint32_t smem_u32(const void* p) {
    uint32_t a;
    asm("{ .reg .u64 t; cvta.to.shared.u64 t, %1; cvt.u32.u64 %0, t; }"
        : "=r"(a) : "l"(p));
    return a;
}
__device__ __forceinline__ void ldsm_x4(uint32_t& r0, uint32_t& r1,
                                        uint32_t& r2, uint32_t& r3, uint32_t a) {
    asm volatile("ldmatrix.sync.aligned.m8n8.x4.shared.b16 {%0,%1,%2,%3}, [%4];"
                 : "=r"(r0), "=r"(r1), "=r"(r2), "=r"(r3) : "r"(a));
}
__device__ __forceinline__ void ldsm_x4_t(uint32_t& r0, uint32_t& r1,
                                          uint32_t& r2, uint32_t& r3, uint32_t a) {
    asm volatile("ldmatrix.sync.aligned.m8n8.x4.trans.shared.b16 {%0,%1,%2,%3}, [%4];"
                 : "=r"(r0), "=r"(r1), "=r"(r2), "=r"(r3) : "r"(a));
}
__device__ __forceinline__ void mma_f16(float* c, const uint32_t* a,
                                        uint32_t b0, uint32_t b1) {
    asm volatile(
        "mma.sync.aligned.m16n8k16.row.col.f32.f16.f16.f32 "
        "{%0,%1,%2,%3},{%4,%5,%6,%7},{%8,%9},{%0,%1,%2,%3};"
        : "+f"(c[0]), "+f"(c[1]), "+f"(c[2]), "+f"(c[3])
        : "r"(a[0]), "r"(a[1]), "r"(a[2]), "r"(a[3]), "r"(b0), "r"(b1));
}
__device__ __forceinline__ uint32_t pack_h2(float a, float b) {
    __half2 h = __floats2half2_rn(a, b);
    return *(uint32_t*)&h;
}

// ---------------- prep kernels ----------------------------------------------
__global__ __launch_bounds__(256) void prep_x(const float* __restrict__ src, int n4)
{
    int i = blockIdx.x * 256 + threadIdx.x;
    if (i < n4) {
        float4 f = ((const float4*)src)[i];
        uint2 u;
        u.x = pack_h2(f.x, f.y);
        u.y = pack_h2(f.z, f.w);
        ((uint2*)g_xc)[i] = u;
    }
}

// dst[n*K + k] = half(src[k*N + n])
__global__ __launch_bounds__(256) void prep_wT(const float* __restrict__ src,
                                               int Kd, int Nd, int which)
{
    __half* dst = which == 0 ? g_wqT : which == 1 ? g_wkT
                : which == 2 ? g_wvT : which == 3 ? g_winT : g_woutT;
    __shared__ float t[32][33];
    int bx = blockIdx.x * 32;   // n
    int by = blockIdx.y * 32;   // k
    int tx = threadIdx.x & 31, ty = threadIdx.x >> 5;
    #pragma unroll
    for (int i = 0; i < 32; i += 8)
        t[ty + i][tx] = src[(size_t)(by + ty + i) * Nd + bx + tx];
    __syncthreads();
    #pragma unroll
    for (int i = 0; i < 32; i += 8)
        dst[(size_t)(bx + ty + i) * Kd + by + tx] = __float2half_rn(t[tx][ty + i]);
}

// =====================================================================
// FP16 tensor-core GEMM: C = epi(A[M,K] @ Bt[N,K]^T + bias)
// BM=128, BN=128, BK=32, 256 threads (8 warps 2x4), warp tile 64x32,
// m16n8k16 mma, ldmatrix fragments, double-buffered cp.async.
// MODE 0: A=g_xc,  Bt=wq/wk/wvT -> g_q/g_k/g_v half (Q scaled 1/8)
// MODE 1: A=g_ln2, Bt=g_winT    -> g_h1 = half(gelu(acc+bias))
// MODE 2: A=g_h1,  Bt=g_woutT   -> Cout = gelu(acc+bias) + g_y  (f32)
// =====================================================================
#define HSTR 40           // halves per smem row (32 + 8 pad), 80B
#define TILEH (128*HSTR)  // halves per tile
#define TILEB (TILEH*2)   // bytes per tile

template<int MODE>
__global__ __launch_bounds__(256) void gemm_fp16(
    const float* __restrict__ bias, float* __restrict__ Cout,
    int N, int K, int which)
{
    __shared__ __half As[2][TILEH];
    __shared__ __half Bs[2][TILEH];

    const __half* A = (MODE == 0) ? g_xc : (MODE == 1 ? g_ln2 : g_h1);
    const __half* Bt = (MODE == 0)
        ? (which == 0 ? g_wqT : (which == 1 ? g_wkT : g_wvT))
        : (MODE == 1 ? g_winT : g_woutT);

    const int tid  = threadIdx.x;
    const int lane = tid & 31;
    const int warp = tid >> 5;
    const int warpM = warp & 1;
    const int warpN = warp >> 1;
    const int quad = lane >> 2;
    const int tkid = lane & 3;

    const int m0 = blockIdx.y * 128;
    const int n0 = blockIdx.x * 128;

    uint32_t sA = smem_u32(&As[0][0]);
    uint32_t sB = smem_u32(&Bs[0][0]);

    const int ld_row = tid >> 2;            // 0..63 (x2 via +64)
    const int ld_c   = (tid & 3) * 8;       // half offset

    auto load_tile = [&](int kt, int buf) {
        const int k0 = kt * 32;
        #pragma unroll
        for (int i = 0; i < 2; i++) {
            int row = ld_row + i * 64;
            cp_async16(sA + buf * TILEB + (row * HSTR + ld_c) * 2,
                       A + (size_t)(m0 + row) * K + k0 + ld_c);
            cp_async16(sB + buf * TILEB + (row * HSTR + ld_c) * 2,
                       Bt + (size_t)(n0 + row) * K + k0 + ld_c);
        }
        asm volatile("cp.async.commit_group;\n");
    };

    float acc[4][4][4];
    #pragma unroll
    for (int i = 0; i < 4; i++)
        #pragma unroll
        for (int j = 0; j < 4; j++)
            #pragma unroll
            for (int r = 0; r < 4; r++) acc[i][j][r] = 0.0f;

    const int KT = K / 32;
    load_tile(0, 0);

    // ldmatrix lane address components
    const int a_r = lane & 15;              // row within 16
    const int a_c = (lane >> 4) * 8;        // k offset 0/8
    const int b_r = ((lane >> 4) * 8) + (lane & 7);  // n row 0..15
    const int b_c = ((lane >> 3) & 1) * 8;  // k offset 0/8

    for (int kt = 0; kt < KT; kt++) {
        const int buf = kt & 1;
        if (kt + 1 < KT) {
            load_tile(kt + 1, buf ^ 1);
            asm volatile("cp.async.wait_group 1;\n");
        } else {
            asm volatile("cp.async.wait_group 0;\n");
        }
        __syncthreads();

        const uint32_t aB = sA + buf * TILEB;
        const uint32_t bB = sB + buf * TILEB;

        #pragma unroll
        for (int ks = 0; ks < 2; ks++) {
            const int kb = ks * 16;
            uint32_t af[4][4];
            #pragma unroll
            for (int tm = 0; tm < 4; tm++) {
                uint32_t addr = aB +
                    ((warpM * 64 + tm * 16 + a_r) * HSTR + kb + a_c) * 2;
                ldsm_x4(af[tm][0], af[tm][1], af[tm][2], af[tm][3], addr);
            }
            uint32_t bf[4][2];
            #pragma unroll
            for (int p = 0; p < 2; p++) {
                uint32_t addr = bB +
                    ((warpN * 32 + p * 16 + b_r) * HSTR + kb + b_c) * 2;
                ldsm_x4(bf[2*p][0], bf[2*p][1], bf[2*p+1][0], bf[2*p+1][1], addr);
            }
            #pragma unroll
            for (int tm = 0; tm < 4; tm++)
                #pragma unroll
                for (int tn = 0; tn < 4; tn++)
                    mma_f16(acc[tm][tn], af[tm], bf[tn][0], bf[tn][1]);
        }
        __syncthreads();
    }

    // ---------------- epilogue ----------------
    __half* qkv_out = (MODE == 0)
        ? (which == 0 ? g_q : (which == 1 ? g_k : g_v)) : nullptr;
    const float qscale = (MODE == 0 && which == 0) ? 0.125f : 1.0f;

    #pragma unroll
    for (int tm = 0; tm < 4; tm++) {
        #pragma unroll
        for (int tn = 0; tn < 4; tn++) {
            const int n = n0 + warpN * 32 + tn * 8 + tkid * 2;
            const float bn0 = bias[n], bn1 = bias[n + 1];
            #pragma unroll
            for (int half_m = 0; half_m < 2; half_m++) {
                const int m = m0 + warpM * 64 + tm * 16 + quad + half_m * 8;
                float v0 = acc[tm][tn][half_m * 2    ] + bn0;
                float v1 = acc[tm][tn][half_m * 2 + 1] + bn1;
                if (MODE == 0) {
                    int b = m >> 10, s = m & 1023;
                    int h = n >> 6, hd = n & 63;
                    uint32_t pk = pack_h2(v0 * qscale, v1 * qscale);
                    *(uint32_t*)&qkv_out[(((size_t)b * Hh + h) * Ss + s) * HDd + hd] = pk;
                } else if (MODE == 1) {
                    uint32_t pk = pack_h2(gelu_exact(v0), gelu_exact(v1));
                    *(uint32_t*)&g_h1[(size_t)m * N + n] = pk;
                } else {
                    const float* rp = g_y + (size_t)m * N + n;
                    float2 o = make_float2(gelu_exact(v0) + rp[0],
                                           gelu_exact(v1) + rp[1]);
                    *(float2*)&Cout[(size_t)m * N + n] = o;
                }
            }
        }
    }
}

// =====================================================================
// FP16 tensor-core flash attention. Block = 64 q rows, 4 warps x 16.
// KV tiles 32 rows double-buffered. P converted in registers (no smem).
// =====================================================================
#define KSTRH 72   // halves per KV smem row (64 + 8 pad), 144B
#define KVTILEH (32*KSTRH)
#define KVTILEB (KVTILEH*2)

__global__ __launch_bounds__(128) void attn_tc(void)
{
    __shared__ __half Ks[2][KVTILEH];
    __shared__ __half Vs[2][KVTILEH];

    const int bh   = blockIdx.y;
    const int tid  = threadIdx.x;
    const int warp = tid >> 5;
    const int lane = tid & 31;
    const int quad = lane >> 2;
    const int tkid = lane & 3;

    const int q0 = blockIdx.x * 64 + warp * 16;
    const __half* qbase = g_q + ((size_t)bh * Ss + q0) * HDd;
    const __half* kbase = g_k + (size_t)bh * Ss * HDd;
    const __half* vbase = g_v + (size_t)bh * Ss * HDd;

    // Q fragments: qf[kb][0..3], kb over 4 d-blocks of 16
    uint32_t qf[4][4];
    #pragma unroll
    for (int kb = 0; kb < 4; kb++) {
        int c = kb * 16 + tkid * 2;
        qf[kb][0] = *(const uint32_t*)&qbase[(quad    ) * HDd + c    ];
        qf[kb][1] = *(const uint32_t*)&qbase[(quad + 8) * HDd + c    ];
        qf[kb][2] = *(const uint32_t*)&qbase[(quad    ) * HDd + c + 8];
        qf[kb][3] = *(const uint32_t*)&qbase[(quad + 8) * HDd + c + 8];
    }

    float o[8][4];
    #pragma unroll
    for (int j = 0; j < 8; j++)
        #pragma unroll
        for (int r = 0; r < 4; r++) o[j][r] = 0.0f;
    float mrow[2] = {-1e30f, -1e30f};
    float lrow[2] = {0.0f, 0.0f};

    uint32_t sK = smem_u32(&Ks[0][0]);
    uint32_t sV = smem_u32(&Vs[0][0]);

    const int ld_row = tid >> 3;          // 0..15 (x2 via +16)
    const int ld_c   = (tid & 7) * 8;

    auto load_tile = [&](int t, int buf) {
        const __half* kp = kbase + (size_t)t * 32 * HDd;
        const __half* vp = vbase + (size_t)t * 32 * HDd;
        #pragma unroll
        for (int i = 0; i < 2; i++) {
            int row = ld_row + i * 16;
            cp_async16(sK + buf * KVTILEB + (row * KSTRH + ld_c) * 2,
                       kp + row * HDd + ld_c);
            cp_async16(sV + buf * KVTILEB + (row * KSTRH + ld_c) * 2,
                       vp + row * HDd + ld_c);
        }
        asm volatile("cp.async.commit_group;\n");
    };

    load_tile(0, 0);
    const int NT = Ss / 32;

    // ldmatrix address components
    const int kb_r = ((lane >> 4) * 8) + (lane & 7);   // s row 0..15 (no trans)
    const int kb_c = ((lane >> 3) & 1) * 8;            // d offset 0/8
    const int vb_r = (((lane >> 3) & 1) * 8) + (lane & 7); // s row (trans)
    const int vb_c = (lane >> 4) * 8;                  // d offset 0/8

    for (int t = 0; t < NT; t++) {
        const int buf = t & 1;
        if (t + 1 < NT) {
            load_tile(t + 1, buf ^ 1);
            asm volatile("cp.async.wait_group 1;\n");
        } else {
            asm volatile("cp.async.wait_group 0;\n");
        }
        __syncthreads();

        const uint32_t kB = sK + buf * KVTILEB;
        const uint32_t vB = sV + buf * KVTILEB;

        // --- S = Q @ K^T : sc[4 s-tiles][4] ---
        float sc[4][4];
        #pragma unroll
        for (int j = 0; j < 4; j++)
            #pragma unroll
            for (int r = 0; r < 4; r++) sc[j][r] = 0.0f;

        #pragma unroll
        for (int kb = 0; kb < 4; kb++) {
            uint32_t bf[4][2];
            #pragma unroll
            for (int p = 0; p < 2; p++) {
                uint32_t addr = kB + ((p * 16 + kb_r) * KSTRH + kb * 16 + kb_c) * 2;
                ldsm_x4(bf[2*p][0], bf[2*p][1], bf[2*p+1][0], bf[2*p+1][1], addr);
            }
            #pragma unroll
            for (int j = 0; j < 4; j++)
                mma_f16(sc[j], qf[kb], bf[j][0], bf[j][1]);
        }

        // --- online softmax ---
        #pragma unroll
        for (int r = 0; r < 2; r++) {
            float tmax = -1e30f;
            #pragma unroll
            for (int j = 0; j < 4; j++)
                tmax = fmaxf(tmax, fmaxf(sc[j][2 * r], sc[j][2 * r + 1]));
            tmax = fmaxf(tmax, __shfl_xor_sync(0xffffffffu, tmax, 1));
            tmax = fmaxf(tmax, __shfl_xor_sync(0xffffffffu, tmax, 2));

            float mnew = fmaxf(mrow[r], tmax);
            float corr = __expf(mrow[r] - mnew);
            mrow[r] = mnew;
            lrow[r] *= corr;
            #pragma unroll
            for (int j = 0; j < 8; j++) {
                o[j][2 * r]     *= corr;
                o[j][2 * r + 1] *= corr;
            }
        }

        // exp in-place; accumulate l
        #pragma unroll
        for (int j = 0; j < 4; j++) {
            sc[j][0] = __expf(sc[j][0] - mrow[0]);
            sc[j][1] = __expf(sc[j][1] - mrow[0]);
            sc[j][2] = __expf(sc[j][2] - mrow[1]);
            sc[j][3] = __expf(sc[j][3] - mrow[1]);
            lrow[0] += sc[j][0] + sc[j][1];
            lrow[1] += sc[j][2] + sc[j][3];
        }

        // --- O += P @ V : P from registers (C->A layout) ---
        #pragma unroll
        for (int th = 0; th < 2; th++) {           // k-blocks of s (16)
            uint32_t af[4];
            af[0] = pack_h2(sc[2*th  ][0], sc[2*th  ][1]);
            af[1] = pack_h2(sc[2*th  ][2], sc[2*th  ][3]);
            af[2] = pack_h2(sc[2*th+1][0], sc[2*th+1][1]);
            af[3] = pack_h2(sc[2*th+1][2], sc[2*th+1][3]);

            #pragma unroll
            for (int p = 0; p < 4; p++) {          // d-tile pairs
                uint32_t vb[2][2];
                uint32_t addr = vB + ((th * 16 + vb_r) * KSTRH + p * 16 + vb_c) * 2;
                ldsm_x4_t(vb[0][0], vb[0][1], vb[1][0], vb[1][1], addr);
                mma_f16(o[2*p  ], af, vb[0][0], vb[0][1]);
                mma_f16(o[2*p+1], af, vb[1][0], vb[1][1]);
            }
        }
        __syncthreads();
    }

    #pragma unroll
    for (int r = 0; r < 2; r++) {
        lrow[r] += __shfl_xor_sync(0xffffffffu, lrow[r], 1);
        lrow[r] += __shfl_xor_sync(0xffffffffu, lrow[r], 2);
    }
    float inv0 = 1.0f / lrow[0];
    float inv1 = 1.0f / lrow[1];

    float* ob0 = g_ctx + ((size_t)bh * Ss + q0 + quad    ) * HDd;
    float* ob1 = g_ctx + ((size_t)bh * Ss + q0 + quad + 8) * HDd;
    #pragma unroll
    for (int j = 0; j < 8; j++) {
        int col = j * 8 + tkid * 2;
        *(float2*)&ob0[col] = make_float2(o[j][0] * inv0, o[j][1] * inv0);
        *(float2*)&ob1[col] = make_float2(o[j][2] * inv1, o[j][3] * inv1);
    }
}

// ---------------- LN1: y = x + LN(ctx[B,H,S,HD]) * g + b --------------------
__global__ __launch_bounds__(256) void ln1_add(
    const float* __restrict__ x, const float* __restrict__ g,
    const float* __restrict__ bta)
{
    const int row = blockIdx.x;
    const int b = row >> 10, s = row & 1023;
    const int tid = threadIdx.x;

    float vals[3];
    float sum = 0.0f, sq = 0.0f;
    #pragma unroll
    for (int i = 0; i < 3; i++) {
        int col = tid + i * 256;
        int h = col >> 6, hd = col & 63;
        float c = g_ctx[(((size_t)b * Hh + h) * Ss + s) * HDd + hd];
        vals[i] = c;
        sum += c;
        sq += c * c;
    }
    __shared__ float rs[256], rq[256];
    rs[tid] = sum; rq[tid] = sq;
    __syncthreads();
    for (int o = 128; o > 0; o >>= 1) {
        if (tid < o) { rs[tid] += rs[tid + o]; rq[tid] += rq[tid + o]; }
        __syncthreads();
    }
    float mu = rs[0] * (1.0f / Dd);
    float var = rq[0] * (1.0f / Dd) - mu * mu;
    float rstd = rsqrtf(var + 1e-5f);
    #pragma unroll
    for (int i = 0; i < 3; i++) {
        int col = tid + i * 256;
        float yv = x[(size_t)row * Dd + col] +
                   (vals[i] - mu) * rstd * g[col] + bta[col];
        g_y[(size_t)row * Dd + col] = yv;
    }
}

// ---------------- LN2: g_ln2 = half(LN(g_y) * g + b) ------------------------
__global__ __launch_bounds__(256) void ln2_kernel(
    const float* __restrict__ g, const float* __restrict__ bta)
{
    const int row = blockIdx.x;
    const int tid = threadIdx.x;

    float vals[3];
    float sum = 0.0f, sq = 0.0f;
    #pragma unroll
    for (int i = 0; i < 3; i++) {
        int col = tid + i * 256;
        float c = g_y[(size_t)row * Dd + col];
        vals[i] = c;
        sum += c;
        sq += c * c;
    }
    __shared__ float rs[256], rq[256];
    rs[tid] = sum; rq[tid] = sq;
    __syncthreads();
    for (int o = 128; o > 0; o >>= 1) {
        if (tid < o) { rs[tid] += rs[tid + o]; rq[tid] += rq[tid + o]; }
        __syncthreads();
    }
    float mu = rs[0] * (1.0f / Dd);
    float var = rq[0] * (1.0f / Dd) - mu * mu;
    float rstd = rsqrtf(var + 1e-5f);
    #pragma unroll
    for (int i = 0; i < 3; i++) {
        int col = tid + i * 256;
        g_ln2[(size_t)row * Dd + col] =
            __float2half_rn((vals[i] - mu) * rstd * g[col] + bta[col]);
    }
}

// ---------------- launch ----------------------------------------------------
extern "C" void kernel_launch(void* const* d_in, const int* in_sizes, int n_in,
                              void* d_out, int out_size)
{
    (void)in_sizes; (void)n_in; (void)out_size;
    const float* x     = (const float*)d_in[0];
    const float* wq    = (const float*)d_in[1];
    const float* bq    = (const float*)d_in[2];
    const float* wk    = (const float*)d_in[3];
    const float* bk    = (const float*)d_in[4];
    const float* wv    = (const float*)d_in[5];
    const float* bv    = (const float*)d_in[6];
    const float* ln1_g = (const float*)d_in[7];
    const float* ln1_b = (const float*)d_in[8];
    const float* ln2_g = (const float*)d_in[9];
    const float* ln2_b = (const float*)d_in[10];
    const float* w_in  = (const float*)d_in[11];
    const float* b_in  = (const float*)d_in[12];
    const float* w_out = (const float*)d_in[13];
    const float* b_out = (const float*)d_in[14];
    float* out = (float*)d_out;

    // prep: fp32 -> fp16 at rest (weights transposed to [N,K])
    prep_x<<<(Mm*Dd/4 + 255)/256, 256>>>(x, Mm*Dd/4);
    prep_wT<<<dim3(Dd/32,  Dd/32),  256>>>(wq,    Dd,   Dd,   0);
    prep_wT<<<dim3(Dd/32,  Dd/32),  256>>>(wk,    Dd,   Dd,   1);
    prep_wT<<<dim3(Dd/32,  Dd/32),  256>>>(wv,    Dd,   Dd,   2);
    prep_wT<<<dim3(HIDh/32, Dd/32), 256>>>(w_in,  Dd,   HIDh, 3);
    prep_wT<<<dim3(Dd/32, HIDh/32), 256>>>(w_out, HIDh, Dd,   4);

    // QKV projections -> [B,H,S,HD] fp16 (Q pre-scaled 1/8)
    dim3 gq(Dd / 128, Mm / 128);
    gemm_fp16<0><<<gq, 256>>>(bq, nullptr, Dd, Dd, 0);
    gemm_fp16<0><<<gq, 256>>>(bk, nullptr, Dd, Dd, 1);
    gemm_fp16<0><<<gq, 256>>>(bv, nullptr, Dd, Dd, 2);

    // attention -> g_ctx f32
    dim3 ga(Ss / 64, Bb * Hh);
    attn_tc<<<ga, 128>>>();

    ln1_add<<<Mm, 256>>>(x, ln1_g, ln1_b);
    ln2_kernel<<<Mm, 256>>>(ln2_g, ln2_b);

    // MLP
    dim3 g1(HIDh / 128, Mm / 128);
    gemm_fp16<1><<<g1, 256>>>(b_in, nullptr, HIDh, Dd, 0);

    dim3 g2(Dd / 128, Mm / 128);
    gemm_fp16<2><<<g2, 256>>>(b_out, out, Dd, HIDh, 0);
}

// round 7
// speedup vs baseline: 1.9549x; 1.0868x over previous
#include <cuda_runtime.h>
#include <cuda_fp16.h>
#include <math.h>
#include <stdint.h>

#define Bb   8
#define Ss   1024
#define Dd   768
#define Hh   12
#define HDd  64
#define HIDh 3072
#define Mm   (Bb*Ss)   // 8192

// ---------------- scratch (device globals; no allocs allowed) ----------------
__device__ __half g_q   [(size_t)Mm*Dd];
__device__ __half g_k   [(size_t)Mm*Dd];
__device__ __half g_v   [(size_t)Mm*Dd];
__device__ __half g_ln2 [(size_t)Mm*Dd];
__device__ __half g_h1  [(size_t)Mm*HIDh];
__device__ __half g_xc  [(size_t)Mm*Dd];
__device__ __half g_wqT [(size_t)Dd*Dd];      // [N,K]
__device__ __half g_wkT [(size_t)Dd*Dd];
__device__ __half g_wvT [(size_t)Dd*Dd];
__device__ __half g_winT[(size_t)HIDh*Dd];    // [3072,768]
__device__ __half g_woutT[(size_t)Dd*HIDh];   // [768,3072]
__device__ float g_ctx[(size_t)Mm*Dd];
__device__ float g_y  [(size_t)Mm*Dd];

__device__ __forceinline__ float gelu_exact(float x) {
    return 0.5f * x * (1.0f + erff(x * 0.70710678118654752f));
}
__device__ __forceinline__ void cp_async16(uint32_t saddr, const void* gaddr) {
    asm volatile("cp.async.cg.shared.global [%0], [%1], 16;\n" :: "r"(saddr), "l"(gaddr));
}
__device__ __forceinline__ uint32_t smem_u32(const void* p) {
    uint32_t a;
    asm("{ .reg .u64 t; cvta.to.shared.u64 t, %1; cvt.u32.u64 %0, t; }"
        : "=r"(a) : "l"(p));
    return a;
}
__device__ __forceinline__ void ldsm_x4(uint32_t& r0, uint32_t& r1,
                                        uint32_t& r2, uint32_t& r3, uint32_t a) {
    asm volatile("ldmatrix.sync.aligned.m8n8.x4.shared.b16 {%0,%1,%2,%3}, [%4];"
                 : "=r"(r0), "=r"(r1), "=r"(r2), "=r"(r3) : "r"(a));
}
__device__ __forceinline__ void ldsm_x4_t(uint32_t& r0, uint32_t& r1,
                                          uint32_t& r2, uint32_t& r3, uint32_t a) {
    asm volatile("ldmatrix.sync.aligned.m8n8.x4.trans.shared.b16 {%0,%1,%2,%3}, [%4];"
                 : "=r"(r0), "=r"(r1), "=r"(r2), "=r"(r3) : "r"(a));
}
__device__ __forceinline__ void mma_f16(float* c, const uint32_t* a,
                                        uint32_t b0, uint32_t b1) {
    asm volatile(
        "mma.sync.aligned.m16n8k16.row.col.f32.f16.f16.f32 "
        "{%0,%1,%2,%3},{%4,%5,%6,%7},{%8,%9},{%0,%1,%2,%3};"
        : "+f"(c[0]), "+f"(c[1]), "+f"(c[2]), "+f"(c[3])
        : "r"(a[0]), "r"(a[1]), "r"(a[2]), "r"(a[3]), "r"(b0), "r"(b1));
}
__device__ __forceinline__ uint32_t pack_h2(float a, float b) {
    __half2 h = __floats2half2_rn(a, b);
    return *(uint32_t*)&h;
}

// ---------------- prep kernels ----------------------------------------------
__global__ __launch_bounds__(256) void prep_x(const float* __restrict__ src, int n4)
{
    int i = blockIdx.x * 256 + threadIdx.x;
    if (i < n4) {
        float4 f = ((const float4*)src)[i];
        uint2 u;
        u.x = pack_h2(f.x, f.y);
        u.y = pack_h2(f.z, f.w);
        ((uint2*)g_xc)[i] = u;
    }
}

// dst[n*K + k] = half(src[k*N + n]); which selects the destination.
__global__ __launch_bounds__(256) void prep_wT(const float* __restrict__ s0,
                                               const float* __restrict__ s1,
                                               const float* __restrict__ s2,
                                               int Kd, int Nd, int mode3)
{
    const float* src = mode3 ? (blockIdx.z == 0 ? s0 : (blockIdx.z == 1 ? s1 : s2)) : s0;
    __half* dst;
    if (mode3) dst = blockIdx.z == 0 ? g_wqT : (blockIdx.z == 1 ? g_wkT : g_wvT);
    else       dst = (Nd == HIDh) ? g_winT : g_woutT;

    __shared__ float t[32][33];
    int bx = blockIdx.x * 32;   // n
    int by = blockIdx.y * 32;   // k
    int tx = threadIdx.x & 31, ty = threadIdx.x >> 5;
    #pragma unroll
    for (int i = 0; i < 32; i += 8)
        t[ty + i][tx] = src[(size_t)(by + ty + i) * Nd + bx + tx];
    __syncthreads();
    #pragma unroll
    for (int i = 0; i < 32; i += 8)
        dst[(size_t)(bx + ty + i) * Kd + by + tx] = __float2half_rn(t[tx][ty + i]);
}

// =====================================================================
// FP16 GEMM v3: CTA 128x128, 4 warps (2x2), warp tile 64x64, BK=32,
// 3-stage cp.async pipeline, dynamic smem.
// MODE 0: A=g_xc,  Bt by blockIdx.z -> g_q/g_k/g_v half (Q scaled 1/8)
// MODE 1: A=g_ln2, Bt=g_winT  -> g_h1 = half(gelu(acc+bias))
// MODE 2: A=g_h1,  Bt=g_woutT -> Cout = gelu(acc+bias) + g_y  (f32)
// =====================================================================
#define HSTR 40                   // halves per smem row (32 + 8 pad)
#define STAGE_H (128*HSTR)        // halves per tensor per stage
#define STAGE_B (STAGE_H*2)
#define NSTAGE 3
#define GSMEM (NSTAGE * STAGE_B * 2)

template<int MODE>
__global__ __launch_bounds__(128) void gemm_fp16(
    const float* __restrict__ bias0, const float* __restrict__ bias1,
    const float* __restrict__ bias2, float* __restrict__ Cout,
    int N, int K)
{
    extern __shared__ __half smem[];
    const int which = (MODE == 0) ? blockIdx.z : 0;

    const __half* A = (MODE == 0) ? g_xc : (MODE == 1 ? g_ln2 : g_h1);
    const __half* Bt = (MODE == 0)
        ? (which == 0 ? g_wqT : (which == 1 ? g_wkT : g_wvT))
        : (MODE == 1 ? g_winT : g_woutT);
    const float* bias = (MODE == 0)
        ? (which == 0 ? bias0 : (which == 1 ? bias1 : bias2)) : bias0;

    const int tid  = threadIdx.x;
    const int lane = tid & 31;
    const int warp = tid >> 5;
    const int warpM = warp & 1;
    const int warpN = warp >> 1;
    const int quad = lane >> 2;
    const int tkid = lane & 3;

    const int m0 = blockIdx.y * 128;
    const int n0 = blockIdx.x * 128;

    uint32_t sA = smem_u32(smem);
    uint32_t sB = sA + NSTAGE * STAGE_B;

    const int ld_row4 = tid >> 2;           // base row (x4 via +128... see loop)
    const int ld_c    = (tid & 3) * 8;

    auto load_tile = [&](int kt, int buf) {
        const int k0 = kt * 32;
        #pragma unroll
        for (int i = 0; i < 4; i++) {
            int idx = tid + i * 128;         // 0..511
            int row = idx >> 2;
            int c8  = (idx & 3) * 8;
            cp_async16(sA + buf * STAGE_B + (row * HSTR + c8) * 2,
                       A + (size_t)(m0 + row) * K + k0 + c8);
            cp_async16(sB + buf * STAGE_B + (row * HSTR + c8) * 2,
                       Bt + (size_t)(n0 + row) * K + k0 + c8);
        }
        asm volatile("cp.async.commit_group;\n");
    };
    (void)ld_row4; (void)ld_c;

    float acc[4][8][4];
    #pragma unroll
    for (int i = 0; i < 4; i++)
        #pragma unroll
        for (int j = 0; j < 8; j++)
            #pragma unroll
            for (int r = 0; r < 4; r++) acc[i][j][r] = 0.0f;

    const int KT = K / 32;

    load_tile(0, 0);
    load_tile(1, 1);
    asm volatile("cp.async.wait_group 1;\n");
    __syncthreads();

    const int a_r = lane & 15;
    const int a_c = (lane >> 4) * 8;
    const int b_r = ((lane >> 4) * 8) + (lane & 7);
    const int b_c = ((lane >> 3) & 1) * 8;

    for (int kt = 0; kt < KT; kt++) {
        const int buf = kt % NSTAGE;
        const uint32_t aB = sA + buf * STAGE_B;
        const uint32_t bB = sB + buf * STAGE_B;

        #pragma unroll
        for (int ks = 0; ks < 2; ks++) {
            const int kb = ks * 16;
            uint32_t af[4][4];
            #pragma unroll
            for (int tm = 0; tm < 4; tm++) {
                uint32_t addr = aB +
                    ((warpM * 64 + tm * 16 + a_r) * HSTR + kb + a_c) * 2;
                ldsm_x4(af[tm][0], af[tm][1], af[tm][2], af[tm][3], addr);
            }
            uint32_t bf[8][2];
            #pragma unroll
            for (int p = 0; p < 4; p++) {
                uint32_t addr = bB +
                    ((warpN * 64 + p * 16 + b_r) * HSTR + kb + b_c) * 2;
                ldsm_x4(bf[2*p][0], bf[2*p][1], bf[2*p+1][0], bf[2*p+1][1], addr);
            }
            #pragma unroll
            for (int tm = 0; tm < 4; tm++)
                #pragma unroll
                for (int tn = 0; tn < 8; tn++)
                    mma_f16(acc[tm][tn], af[tm], bf[tn][0], bf[tn][1]);
        }
        __syncthreads();

        if (kt + 2 < KT) {
            load_tile(kt + 2, (kt + 2) % NSTAGE);
            asm volatile("cp.async.wait_group 1;\n");
            __syncthreads();
        } else if (kt + 1 < KT) {
            asm volatile("cp.async.wait_group 0;\n");
            __syncthreads();
        }
    }

    // ---------------- epilogue ----------------
    __half* qkv_out = (MODE == 0)
        ? (which == 0 ? g_q : (which == 1 ? g_k : g_v)) : nullptr;
    const float qscale = (MODE == 0 && which == 0) ? 0.125f : 1.0f;

    #pragma unroll
    for (int tm = 0; tm < 4; tm++) {
        #pragma unroll
        for (int tn = 0; tn < 8; tn++) {
            const int n = n0 + warpN * 64 + tn * 8 + tkid * 2;
            const float bn0 = bias[n], bn1 = bias[n + 1];
            #pragma unroll
            for (int half_m = 0; half_m < 2; half_m++) {
                const int m = m0 + warpM * 64 + tm * 16 + quad + half_m * 8;
                float v0 = acc[tm][tn][half_m * 2    ] + bn0;
                float v1 = acc[tm][tn][half_m * 2 + 1] + bn1;
                if (MODE == 0) {
                    int b = m >> 10, s = m & 1023;
                    int h = n >> 6, hd = n & 63;
                    uint32_t pk = pack_h2(v0 * qscale, v1 * qscale);
                    *(uint32_t*)&qkv_out[(((size_t)b * Hh + h) * Ss + s) * HDd + hd] = pk;
                } else if (MODE == 1) {
                    uint32_t pk = pack_h2(gelu_exact(v0), gelu_exact(v1));
                    *(uint32_t*)&g_h1[(size_t)m * N + n] = pk;
                } else {
                    const float* rp = g_y + (size_t)m * N + n;
                    float2 o = make_float2(gelu_exact(v0) + rp[0],
                                           gelu_exact(v1) + rp[1]);
                    *(float2*)&Cout[(size_t)m * N + n] = o;
                }
            }
        }
    }
}

// =====================================================================
// FP16 tensor-core flash attention (validated round 6, unchanged)
// =====================================================================
#define KSTRH 72
#define KVTILEH (32*KSTRH)
#define KVTILEB (KVTILEH*2)

__global__ __launch_bounds__(128) void attn_tc(void)
{
    __shared__ __half Ks[2][KVTILEH];
    __shared__ __half Vs[2][KVTILEH];

    const int bh   = blockIdx.y;
    const int tid  = threadIdx.x;
    const int warp = tid >> 5;
    const int lane = tid & 31;
    const int quad = lane >> 2;
    const int tkid = lane & 3;

    const int q0 = blockIdx.x * 64 + warp * 16;
    const __half* qbase = g_q + ((size_t)bh * Ss + q0) * HDd;
    const __half* kbase = g_k + (size_t)bh * Ss * HDd;
    const __half* vbase = g_v + (size_t)bh * Ss * HDd;

    uint32_t qf[4][4];
    #pragma unroll
    for (int kb = 0; kb < 4; kb++) {
        int c = kb * 16 + tkid * 2;
        qf[kb][0] = *(const uint32_t*)&qbase[(quad    ) * HDd + c    ];
        qf[kb][1] = *(const uint32_t*)&qbase[(quad + 8) * HDd + c    ];
        qf[kb][2] = *(const uint32_t*)&qbase[(quad    ) * HDd + c + 8];
        qf[kb][3] = *(const uint32_t*)&qbase[(quad + 8) * HDd + c + 8];
    }

    float o[8][4];
    #pragma unroll
    for (int j = 0; j < 8; j++)
        #pragma unroll
        for (int r = 0; r < 4; r++) o[j][r] = 0.0f;
    float mrow[2] = {-1e30f, -1e30f};
    float lrow[2] = {0.0f, 0.0f};

    uint32_t sK = smem_u32(&Ks[0][0]);
    uint32_t sV = smem_u32(&Vs[0][0]);

    const int ld_row = tid >> 3;
    const int ld_c   = (tid & 7) * 8;

    auto load_tile = [&](int t, int buf) {
        const __half* kp = kbase + (size_t)t * 32 * HDd;
        const __half* vp = vbase + (size_t)t * 32 * HDd;
        #pragma unroll
        for (int i = 0; i < 2; i++) {
            int row = ld_row + i * 16;
            cp_async16(sK + buf * KVTILEB + (row * KSTRH + ld_c) * 2,
                       kp + row * HDd + ld_c);
            cp_async16(sV + buf * KVTILEB + (row * KSTRH + ld_c) * 2,
                       vp + row * HDd + ld_c);
        }
        asm volatile("cp.async.commit_group;\n");
    };

    load_tile(0, 0);
    const int NT = Ss / 32;

    const int kb_r = ((lane >> 4) * 8) + (lane & 7);
    const int kb_c = ((lane >> 3) & 1) * 8;
    const int vb_r = (((lane >> 3) & 1) * 8) + (lane & 7);
    const int vb_c = (lane >> 4) * 8;

    for (int t = 0; t < NT; t++) {
        const int buf = t & 1;
        if (t + 1 < NT) {
            load_tile(t + 1, buf ^ 1);
            asm volatile("cp.async.wait_group 1;\n");
        } else {
            asm volatile("cp.async.wait_group 0;\n");
        }
        __syncthreads();

        const uint32_t kB = sK + buf * KVTILEB;
        const uint32_t vB = sV + buf * KVTILEB;

        float sc[4][4];
        #pragma unroll
        for (int j = 0; j < 4; j++)
            #pragma unroll
            for (int r = 0; r < 4; r++) sc[j][r] = 0.0f;

        #pragma unroll
        for (int kb = 0; kb < 4; kb++) {
            uint32_t bf[4][2];
            #pragma unroll
            for (int p = 0; p < 2; p++) {
                uint32_t addr = kB + ((p * 16 + kb_r) * KSTRH + kb * 16 + kb_c) * 2;
                ldsm_x4(bf[2*p][0], bf[2*p][1], bf[2*p+1][0], bf[2*p+1][1], addr);
            }
            #pragma unroll
            for (int j = 0; j < 4; j++)
                mma_f16(sc[j], qf[kb], bf[j][0], bf[j][1]);
        }

        #pragma unroll
        for (int r = 0; r < 2; r++) {
            float tmax = -1e30f;
            #pragma unroll
            for (int j = 0; j < 4; j++)
                tmax = fmaxf(tmax, fmaxf(sc[j][2 * r], sc[j][2 * r + 1]));
            tmax = fmaxf(tmax, __shfl_xor_sync(0xffffffffu, tmax, 1));
            tmax = fmaxf(tmax, __shfl_xor_sync(0xffffffffu, tmax, 2));

            float mnew = fmaxf(mrow[r], tmax);
            float corr = __expf(mrow[r] - mnew);
            mrow[r] = mnew;
            lrow[r] *= corr;
            #pragma unroll
            for (int j = 0; j < 8; j++) {
                o[j][2 * r]     *= corr;
                o[j][2 * r + 1] *= corr;
            }
        }

        #pragma unroll
        for (int j = 0; j < 4; j++) {
            sc[j][0] = __expf(sc[j][0] - mrow[0]);
            sc[j][1] = __expf(sc[j][1] - mrow[0]);
            sc[j][2] = __expf(sc[j][2] - mrow[1]);
            sc[j][3] = __expf(sc[j][3] - mrow[1]);
            lrow[0] += sc[j][0] + sc[j][1];
            lrow[1] += sc[j][2] + sc[j][3];
        }

        #pragma unroll
        for (int th = 0; th < 2; th++) {
            uint32_t af[4];
            af[0] = pack_h2(sc[2*th  ][0], sc[2*th  ][1]);
            af[1] = pack_h2(sc[2*th  ][2], sc[2*th  ][3]);
            af[2] = pack_h2(sc[2*th+1][0], sc[2*th+1][1]);
            af[3] = pack_h2(sc[2*th+1][2], sc[2*th+1][3]);

            #pragma unroll
            for (int p = 0; p < 4; p++) {
                uint32_t vb[2][2];
                uint32_t addr = vB + ((th * 16 + vb_r) * KSTRH + p * 16 + vb_c) * 2;
                ldsm_x4_t(vb[0][0], vb[0][1], vb[1][0], vb[1][1], addr);
                mma_f16(o[2*p  ], af, vb[0][0], vb[0][1]);
                mma_f16(o[2*p+1], af, vb[1][0], vb[1][1]);
            }
        }
        __syncthreads();
    }

    #pragma unroll
    for (int r = 0; r < 2; r++) {
        lrow[r] += __shfl_xor_sync(0xffffffffu, lrow[r], 1);
        lrow[r] += __shfl_xor_sync(0xffffffffu, lrow[r], 2);
    }
    float inv0 = 1.0f / lrow[0];
    float inv1 = 1.0f / lrow[1];

    float* ob0 = g_ctx + ((size_t)bh * Ss + q0 + quad    ) * HDd;
    float* ob1 = g_ctx + ((size_t)bh * Ss + q0 + quad + 8) * HDd;
    #pragma unroll
    for (int j = 0; j < 8; j++) {
        int col = j * 8 + tkid * 2;
        *(float2*)&ob0[col] = make_float2(o[j][0] * inv0, o[j][1] * inv0);
        *(float2*)&ob1[col] = make_float2(o[j][2] * inv1, o[j][3] * inv1);
    }
}

// ---------------- fused LN1+LN2 ---------------------------------------------
// y = x + LN1(ctx); g_y = y (f32); g_ln2 = half(LN2(y))
__global__ __launch_bounds__(256) void ln_fused(
    const float* __restrict__ x,
    const float* __restrict__ g1, const float* __restrict__ b1,
    const float* __restrict__ g2, const float* __restrict__ b2)
{
    const int row = blockIdx.x;
    const int b = row >> 10, s = row & 1023;
    const int tid = threadIdx.x;

    __shared__ float rs[256], rq[256];

    // --- phase 1: LN of ctx ---
    float cv[3];
    float sum = 0.0f, sq = 0.0f;
    #pragma unroll
    for (int i = 0; i < 3; i++) {
        int col = tid + i * 256;
        int h = col >> 6, hd = col & 63;
        float c = g_ctx[(((size_t)b * Hh + h) * Ss + s) * HDd + hd];
        cv[i] = c;
        sum += c; sq += c * c;
    }
    rs[tid] = sum; rq[tid] = sq;
    __syncthreads();
    for (int o = 128; o > 0; o >>= 1) {
        if (tid < o) { rs[tid] += rs[tid + o]; rq[tid] += rq[tid + o]; }
        __syncthreads();
    }
    float mu = rs[0] * (1.0f / Dd);
    float var = rq[0] * (1.0f / Dd) - mu * mu;
    float rstd = rsqrtf(var + 1e-5f);

    float yv[3];
    float sum2 = 0.0f, sq2 = 0.0f;
    #pragma unroll
    for (int i = 0; i < 3; i++) {
        int col = tid + i * 256;
        float y = x[(size_t)row * Dd + col] +
                  (cv[i] - mu) * rstd * g1[col] + b1[col];
        yv[i] = y;
        sum2 += y; sq2 += y * y;
        g_y[(size_t)row * Dd + col] = y;
    }
    __syncthreads();
    rs[tid] = sum2; rq[tid] = sq2;
    __syncthreads();
    for (int o = 128; o > 0; o >>= 1) {
        if (tid < o) { rs[tid] += rs[tid + o]; rq[tid] += rq[tid + o]; }
        __syncthreads();
    }
    float mu2 = rs[0] * (1.0f / Dd);
    float var2 = rq[0] * (1.0f / Dd) - mu2 * mu2;
    float rstd2 = rsqrtf(var2 + 1e-5f);

    #pragma unroll
    for (int i = 0; i < 3; i++) {
        int col = tid + i * 256;
        g_ln2[(size_t)row * Dd + col] =
            __float2half_rn((yv[i] - mu2) * rstd2 * g2[col] + b2[col]);
    }
}

// ---------------- launch ----------------------------------------------------
extern "C" void kernel_launch(void* const* d_in, const int* in_sizes, int n_in,
                              void* d_out, int out_size)
{
    (void)in_sizes; (void)n_in; (void)out_size;
    const float* x     = (const float*)d_in[0];
    const float* wq    = (const float*)d_in[1];
    const float* bq    = (const float*)d_in[2];
    const float* wk    = (const float*)d_in[3];
    const float* bk    = (const float*)d_in[4];
    const float* wv    = (const float*)d_in[5];
    const float* bv    = (const float*)d_in[6];
    const float* ln1_g = (const float*)d_in[7];
    const float* ln1_b = (const float*)d_in[8];
    const float* ln2_g = (const float*)d_in[9];
    const float* ln2_b = (const float*)d_in[10];
    const float* w_in  = (const float*)d_in[11];
    const float* b_in  = (const float*)d_in[12];
    const float* w_out = (const float*)d_in[13];
    const float* b_out = (const float*)d_in[14];
    float* out = (float*)d_out;

    static int configured = 0;
    if (!configured) {
        cudaFuncSetAttribute(gemm_fp16<0>, cudaFuncAttributeMaxDynamicSharedMemorySize, GSMEM);
        cudaFuncSetAttribute(gemm_fp16<1>, cudaFuncAttributeMaxDynamicSharedMemorySize, GSMEM);
        cudaFuncSetAttribute(gemm_fp16<2>, cudaFuncAttributeMaxDynamicSharedMemorySize, GSMEM);
        configured = 1;
    }

    // prep: fp32 -> fp16 at rest (weights transposed to [N,K])
    prep_x<<<(Mm*Dd/4 + 255)/256, 256>>>(x, Mm*Dd/4);
    prep_wT<<<dim3(Dd/32,  Dd/32, 3), 256>>>(wq, wk, wv, Dd, Dd, 1);
    prep_wT<<<dim3(HIDh/32, Dd/32), 256>>>(w_in,  nullptr, nullptr, Dd,   HIDh, 0);
    prep_wT<<<dim3(Dd/32, HIDh/32), 256>>>(w_out, nullptr, nullptr, HIDh, Dd,   0);

    // QKV projections (one launch, z = q/k/v) -> [B,H,S,HD] fp16
    dim3 gq(Dd / 128, Mm / 128, 3);
    gemm_fp16<0><<<gq, 128, GSMEM>>>(bq, bk, bv, nullptr, Dd, Dd);

    // attention -> g_ctx f32
    dim3 ga(Ss / 64, Bb * Hh);
    attn_tc<<<ga, 128>>>();

    // fused LN1 + LN2
    ln_fused<<<Mm, 256>>>(x, ln1_g, ln1_b, ln2_g, ln2_b);

    // MLP
    dim3 g1(HIDh / 128, Mm / 128);
    gemm_fp16<1><<<g1, 128, GSMEM>>>(b_in, nullptr, nullptr, nullptr, HIDh, Dd);

    dim3 g2(Dd / 128, Mm / 128);
    gemm_fp16<2><<<g2, 128, GSMEM>>>(b_out, nullptr, nullptr, out, Dd, HIDh);
}